// round 5
// baseline (speedup 1.0000x reference)
#include <cuda_runtime.h>
#include <cuda_bf16.h>

#define N_NODES 50000
#define N_EDGES 800000
#define IN_CH   256
#define OUT_CH  128

// ---------------- scratch (device globals; no allocation allowed) -----------
__device__ __align__(128) float g_support[N_NODES * OUT_CH];
__device__ __align__(128) float g_gate[N_NODES * OUT_CH];
__device__ int   g_counts[N_NODES];
__device__ int   g_cursor[N_NODES];
__device__ int   g_row_ptr[N_NODES + 1];
__device__ __align__(128) int2 g_pairs[N_EDGES];  // (col, val-as-int) interleaved
__device__ int   g_is64;   // 1 if edge index arrays are int64, 0 if int32

// Decode edge index i from a buffer of unknown (int32 vs int64) dtype.
__device__ __forceinline__ int load_idx(const void* p, int i, int is64) {
    if (is64) return (int)((const long long*)p)[i];
    return ((const int*)p)[i];
}

// ---------------- dtype detect (device-side, graph-capturable) --------------
// int64 indices < 50000: odd 32-bit words all zero. int32 indices: odd words
// are random node ids; 64 consecutive all-zero has probability ~(2e-5)^64.
__global__ void detect_kernel(const unsigned int* __restrict__ rows_u32) {
    if (threadIdx.x == 0) {
        int all_zero = 1;
        for (int i = 0; i < 64; i++)
            if (rows_u32[2 * i + 1] != 0u) { all_zero = 0; break; }
        g_is64 = all_zero;
    }
}

// ---------------- packed fp32x2 helpers (sm_100+) ---------------------------
__device__ __forceinline__ unsigned long long fma2(unsigned long long a,
                                                   unsigned long long b,
                                                   unsigned long long c) {
    unsigned long long d;
    asm("fma.rn.f32x2 %0, %1, %2, %3;" : "=l"(d) : "l"(a), "l"(b), "l"(c));
    return d;
}
__device__ __forceinline__ unsigned long long pack2(float x, float y) {
    unsigned long long d;
    asm("mov.b64 %0, {%1, %2};" : "=l"(d) : "f"(x), "f"(y));
    return d;
}
__device__ __forceinline__ void unpack2(unsigned long long d, float& x, float& y) {
    asm("mov.b64 {%0, %1}, %2;" : "=f"(x), "=f"(y) : "l"(d));
}

// ---------------- fused dual GEMM: support = X@W, gate = X@G ----------------
// Block: 64 rows x 128 cols (full out width), 256 threads.
// Thread: 4 rows x 8 cols x 2 matrices. f32x2 packed FMA.
__global__ __launch_bounds__(256) void gemm_kernel(
    const float* __restrict__ X,
    const float* __restrict__ W,
    const float* __restrict__ G)
{
    __shared__ __align__(16) float xs[16][64];    // [k][row]
    __shared__ __align__(16) float ws[16 * 128];  // [k][col] flat
    __shared__ __align__(16) float gs[16 * 128];

    const int tid  = threadIdx.x;
    const int row0 = blockIdx.x * 64;
    const int tx   = tid & 15;   // col group: cols tx*4..+3 and 64+tx*4..+3
    const int ty   = tid >> 4;   // row group: rows ty*4..+3
    const int lr   = tid >> 2;   // loader row 0..63
    const int lc   = tid & 3;    // loader k group 0..3

    unsigned long long accS[4][4];
    unsigned long long accG[4][4];
#pragma unroll
    for (int r = 0; r < 4; r++)
#pragma unroll
        for (int p = 0; p < 4; p++) { accS[r][p] = 0ull; accG[r][p] = 0ull; }

    for (int kc = 0; kc < IN_CH; kc += 16) {
        // Stage global loads in registers (overlaps with previous compute).
        // W/G tiles are 16x128 = 2048 floats; 256 threads load 2 float4 each.
        float4 xv = make_float4(0.f, 0.f, 0.f, 0.f);
        int gr = row0 + lr;
        if (gr < N_NODES)
            xv = *(const float4*)&X[(long)gr * IN_CH + kc + lc * 4];
        float4 wv0 = *(const float4*)&W[(kc + 0) * OUT_CH + tid * 4];
        float4 wv1 = *(const float4*)&W[(kc + 8) * OUT_CH + tid * 4];
        float4 gv0 = *(const float4*)&G[(kc + 0) * OUT_CH + tid * 4];
        float4 gv1 = *(const float4*)&G[(kc + 8) * OUT_CH + tid * 4];

        __syncthreads();  // previous tile consumed
        xs[lc * 4 + 0][lr] = xv.x;
        xs[lc * 4 + 1][lr] = xv.y;
        xs[lc * 4 + 2][lr] = xv.z;
        xs[lc * 4 + 3][lr] = xv.w;
        *(float4*)&ws[tid * 4]        = wv0;
        *(float4*)&ws[1024 + tid * 4] = wv1;
        *(float4*)&gs[tid * 4]        = gv0;
        *(float4*)&gs[1024 + tid * 4] = gv1;
        __syncthreads();

#pragma unroll
        for (int kk = 0; kk < 16; kk++) {
            float4 a = *(const float4*)&xs[kk][ty * 4];
            ulonglong2 w0 = *(const ulonglong2*)&ws[kk * 128 + tx * 4];
            ulonglong2 w1 = *(const ulonglong2*)&ws[kk * 128 + 64 + tx * 4];
            ulonglong2 g0 = *(const ulonglong2*)&gs[kk * 128 + tx * 4];
            ulonglong2 g1 = *(const ulonglong2*)&gs[kk * 128 + 64 + tx * 4];
            unsigned long long a2[4];
            a2[0] = pack2(a.x, a.x);
            a2[1] = pack2(a.y, a.y);
            a2[2] = pack2(a.z, a.z);
            a2[3] = pack2(a.w, a.w);
#pragma unroll
            for (int r = 0; r < 4; r++) {
                accS[r][0] = fma2(a2[r], w0.x, accS[r][0]);
                accS[r][1] = fma2(a2[r], w0.y, accS[r][1]);
                accS[r][2] = fma2(a2[r], w1.x, accS[r][2]);
                accS[r][3] = fma2(a2[r], w1.y, accS[r][3]);
                accG[r][0] = fma2(a2[r], g0.x, accG[r][0]);
                accG[r][1] = fma2(a2[r], g0.y, accG[r][1]);
                accG[r][2] = fma2(a2[r], g1.x, accG[r][2]);
                accG[r][3] = fma2(a2[r], g1.y, accG[r][3]);
            }
        }
    }

#pragma unroll
    for (int r = 0; r < 4; r++) {
        int orow = row0 + ty * 4 + r;
        if (orow >= N_NODES) break;
        float4 o;
        unpack2(accS[r][0], o.x, o.y); unpack2(accS[r][1], o.z, o.w);
        *(float4*)&g_support[(long)orow * OUT_CH + tx * 4] = o;
        unpack2(accS[r][2], o.x, o.y); unpack2(accS[r][3], o.z, o.w);
        *(float4*)&g_support[(long)orow * OUT_CH + 64 + tx * 4] = o;
        unpack2(accG[r][0], o.x, o.y); unpack2(accG[r][1], o.z, o.w);
        *(float4*)&g_gate[(long)orow * OUT_CH + tx * 4] = o;
        unpack2(accG[r][2], o.x, o.y); unpack2(accG[r][3], o.z, o.w);
        *(float4*)&g_gate[(long)orow * OUT_CH + 64 + tx * 4] = o;
    }
}

// ---------------- CSR build ------------------------------------------------
__global__ void zero_counts_kernel() {
    int i = blockIdx.x * blockDim.x + threadIdx.x;
    if (i < N_NODES) g_counts[i] = 0;
}

__global__ void hist_kernel(const void* __restrict__ rows) {
    int i = blockIdx.x * blockDim.x + threadIdx.x;
    if (i < N_EDGES) {
        int r = load_idx(rows, i, g_is64);
        if ((unsigned)r < (unsigned)N_NODES)  // defensive
            atomicAdd(&g_counts[r], 1);
    }
}

// Single-block exclusive scan over g_counts -> g_row_ptr / g_cursor.
__global__ __launch_bounds__(1024) void scan_kernel() {
    __shared__ int s_warp[32];
    __shared__ int s_total;
    const int tid = threadIdx.x, lane = tid & 31, wid = tid >> 5;
    int carry = 0;
    for (int base = 0; base < N_NODES; base += 1024) {
        int i = base + tid;
        int v = (i < N_NODES) ? g_counts[i] : 0;
        int sum = v;
#pragma unroll
        for (int off = 1; off < 32; off <<= 1) {
            int n = __shfl_up_sync(0xffffffffu, sum, off);
            if (lane >= off) sum += n;
        }
        if (lane == 31) s_warp[wid] = sum;
        __syncthreads();
        if (wid == 0) {
            int w = s_warp[lane];
            int iw = w;
#pragma unroll
            for (int off = 1; off < 32; off <<= 1) {
                int n = __shfl_up_sync(0xffffffffu, iw, off);
                if (lane >= off) iw += n;
            }
            s_warp[lane] = iw - w;  // exclusive warp offsets
            if (lane == 31) s_total = iw;
        }
        __syncthreads();
        int excl = carry + s_warp[wid] + (sum - v);
        if (i < N_NODES) { g_row_ptr[i] = excl; g_cursor[i] = excl; }
        carry += s_total;
        __syncthreads();  // protect s_warp/s_total for next chunk
    }
    if (tid == 0) g_row_ptr[N_NODES] = carry;
}

__global__ void scatter_kernel(const void* __restrict__ rows,
                               const void* __restrict__ cols,
                               const float* __restrict__ vals) {
    int i = blockIdx.x * blockDim.x + threadIdx.x;
    if (i < N_EDGES) {
        int is64 = g_is64;
        int r = load_idx(rows, i, is64);
        int c = load_idx(cols, i, is64);
        if ((unsigned)r >= (unsigned)N_NODES) return;      // defensive
        int p = atomicAdd(&g_cursor[r], 1);
        if ((unsigned)p < (unsigned)N_EDGES) {             // defensive
            g_pairs[p] = make_int2(c, __float_as_int(vals[i]));
        }
    }
}

// ---------------- gather SpMM + gating -------------------------------------
// One warp per output row; lane handles 4 channels (float4).
// Next-edge (col,val) prefetch breaks the per-iteration load->gather serial
// dependency (raises MLP so L2 latency overlaps across edges).
__global__ __launch_bounds__(256) void spmm_kernel(float* __restrict__ out) {
    int warp_id = (blockIdx.x * blockDim.x + threadIdx.x) >> 5;
    int lane = threadIdx.x & 31;
    if (warp_id >= N_NODES) return;
    int s = g_row_ptr[warp_id];
    int e = g_row_ptr[warp_id + 1];
    int c4 = lane * 4;
    float4 aS = make_float4(0.f, 0.f, 0.f, 0.f);
    float4 aG = make_float4(0.f, 0.f, 0.f, 0.f);

    int2 np = make_int2(0, 0);
    if (s < e) np = g_pairs[s];
#pragma unroll 2
    for (int i = s; i < e; i++) {
        int   c = np.x;
        float v = __int_as_float(np.y);
        if (i + 1 < e) np = g_pairs[i + 1];
        float4 sv = *(const float4*)&g_support[(long)c * OUT_CH + c4];
        float4 gv = *(const float4*)&g_gate[(long)c * OUT_CH + c4];
        aS.x += v * sv.x; aS.y += v * sv.y; aS.z += v * sv.z; aS.w += v * sv.w;
        aG.x += v * gv.x; aG.y += v * gv.y; aG.z += v * gv.z; aG.w += v * gv.w;
    }
    float4 o;
    o.x = aS.x / (1.0f + __expf(-aG.x));
    o.y = aS.y / (1.0f + __expf(-aG.y));
    o.z = aS.z / (1.0f + __expf(-aG.z));
    o.w = aS.w / (1.0f + __expf(-aG.w));
    *(float4*)&out[(long)warp_id * OUT_CH + c4] = o;
}

// ---------------- launch ----------------------------------------------------
extern "C" void kernel_launch(void* const* d_in, const int* in_sizes, int n_in,
                              void* d_out, int out_size) {
    const float* x   = (const float*)d_in[0];
    const void*  er  = d_in[1];
    const void*  ec  = d_in[2];
    const float* ev  = (const float*)d_in[3];
    const float* w   = (const float*)d_in[4];
    const float* gw  = (const float*)d_in[5];
    float* out = (float*)d_out;

    detect_kernel<<<1, 32>>>((const unsigned int*)er);
    gemm_kernel<<<(N_NODES + 63) / 64, 256>>>(x, w, gw);
    zero_counts_kernel<<<(N_NODES + 255) / 256, 256>>>();
    hist_kernel<<<(N_EDGES + 255) / 256, 256>>>(er);
    scan_kernel<<<1, 1024>>>();
    scatter_kernel<<<(N_EDGES + 255) / 256, 256>>>(er, ec, ev);
    spmm_kernel<<<(N_NODES * 32 + 255) / 256, 256>>>(out);
}

// round 8
// speedup vs baseline: 1.3793x; 1.3793x over previous
#include <cuda_runtime.h>
#include <cuda_bf16.h>
#include <cstdint>

#define N_NODES 50000
#define N_EDGES 800000
#define IN_CH   256
#define OUT_CH  128

// ---------------- scratch (device globals; no allocation allowed) -----------
__device__ __align__(128) float g_support[N_NODES * OUT_CH];
__device__ __align__(128) float g_gate[N_NODES * OUT_CH];
__device__ int   g_counts[N_NODES];
__device__ int   g_cursor[N_NODES];
__device__ int   g_row_ptr[N_NODES + 1];
__device__ __align__(128) int2 g_pairs[N_EDGES];  // (col, val-as-int)
__device__ int   g_is64;
// W/G transposed [N=128, K=256] bf16 hi/lo splits
__device__ __align__(128) __nv_bfloat16 g_wt_hi[OUT_CH * IN_CH];
__device__ __align__(128) __nv_bfloat16 g_wt_lo[OUT_CH * IN_CH];
__device__ __align__(128) __nv_bfloat16 g_gt_hi[OUT_CH * IN_CH];
__device__ __align__(128) __nv_bfloat16 g_gt_lo[OUT_CH * IN_CH];

// ---------------- helpers ----------------------------------------------------
__device__ __forceinline__ uint32_t smem_u32(const void* p) {
    uint32_t a;
    asm("{ .reg .u64 t; cvta.to.shared.u64 t, %1; cvt.u32.u64 %0, t; }"
        : "=r"(a) : "l"(p));
    return a;
}

__device__ __forceinline__ void ldsm_x4(uint32_t* r, uint32_t addr) {
    asm volatile("ldmatrix.sync.aligned.m8n8.x4.shared.b16 {%0,%1,%2,%3}, [%4];"
                 : "=r"(r[0]), "=r"(r[1]), "=r"(r[2]), "=r"(r[3]) : "r"(addr));
}

__device__ __forceinline__ void mma16816(float* c, const uint32_t* a, const uint32_t* b) {
    asm volatile(
        "mma.sync.aligned.m16n8k16.row.col.f32.bf16.bf16.f32 "
        "{%0,%1,%2,%3}, {%4,%5,%6,%7}, {%8,%9}, {%0,%1,%2,%3};"
        : "+f"(c[0]), "+f"(c[1]), "+f"(c[2]), "+f"(c[3])
        : "r"(a[0]), "r"(a[1]), "r"(a[2]), "r"(a[3]), "r"(b[0]), "r"(b[1]));
}

// Decode edge index of unknown (int32 vs int64) dtype.
__device__ __forceinline__ int load_idx(const void* p, int i, int is64) {
    if (is64) return (int)((const long long*)p)[i];
    return ((const int*)p)[i];
}

// ---------------- dtype detect ----------------------------------------------
__global__ void detect_kernel(const unsigned int* __restrict__ rows_u32) {
    if (threadIdx.x == 0) {
        int all_zero = 1;
        for (int i = 0; i < 64; i++)
            if (rows_u32[2 * i + 1] != 0u) { all_zero = 0; break; }
        g_is64 = all_zero;
    }
}

// ---------------- W/G prep: transpose + bf16 hi/lo split ---------------------
__global__ void prep_w_kernel(const float* __restrict__ W, const float* __restrict__ G) {
    int i = blockIdx.x * blockDim.x + threadIdx.x;
    if (i >= IN_CH * OUT_CH) return;
    int k = i >> 7;    // 0..255
    int n = i & 127;   // 0..127
    float w = W[i];
    __nv_bfloat16 wh = __float2bfloat16(w);
    __nv_bfloat16 wl = __float2bfloat16(w - __bfloat162float(wh));
    g_wt_hi[n * IN_CH + k] = wh;
    g_wt_lo[n * IN_CH + k] = wl;
    float g = G[i];
    __nv_bfloat16 gh = __float2bfloat16(g);
    __nv_bfloat16 gl = __float2bfloat16(g - __bfloat162float(gh));
    g_gt_hi[n * IN_CH + k] = gh;
    g_gt_lo[n * IN_CH + k] = gl;
}

// ---------------- mma.sync dual GEMM (bf16x3 split) -------------------------
// CTA: 128 rows x 256 cols (cols 0-127 -> support, 128-255 -> gate).
// 8 warps in 2(m) x 4(n) grid; warp tile 64x64; mma.m16n8k16 bf16.
#define KC        64
#define NCHUNK    (IN_CH / KC)   // 4
#define AST       72             // smem stride (elems) for 64-col tiles
#define SM_A_HI   0
#define SM_A_LO   (128 * AST * 2)            // 18432
#define SM_B_HI   (2 * 128 * AST * 2)        // 36864
#define SM_B_LO   (SM_B_HI + 256 * AST * 2)  // 73728
#define GEMM_SMEM (SM_B_LO + 256 * AST * 2)  // 110592

__global__ __launch_bounds__(256) void gemm_mma_kernel(const float* __restrict__ X) {
    extern __shared__ char smem[];
    const uint32_t sb = smem_u32(smem);
    const int tid  = threadIdx.x;
    const int wid  = tid >> 5;
    const int lane = tid & 31;
    const int wm   = wid & 1;    // m-tile 0..1 (64 rows each)
    const int wn   = wid >> 1;   // n-tile 0..3 (64 cols each)
    const int row0 = blockIdx.x * 128;

    float acc[4][8][4];
#pragma unroll
    for (int mf = 0; mf < 4; mf++)
#pragma unroll
        for (int nf = 0; nf < 8; nf++)
#pragma unroll
            for (int q = 0; q < 4; q++) acc[mf][nf][q] = 0.f;

    // ldmatrix lane addresses (element offsets; x2 bytes at use)
    const int a_r = lane & 15, a_c = (lane >> 4) << 3;          // A: 16x16 quads
    const int b_q = lane >> 3;                                   // B: quad id
    const int b_r = ((b_q >> 1) << 3) + (lane & 7);              // n offset
    const int b_c = (b_q & 1) << 3;                              // k offset

    for (int c = 0; c < NCHUNK; c++) {
        const int kc = c * KC;
        __syncthreads();  // previous chunk's compute done before overwrite

        // ---- A: 128x64 fp32 -> bf16 hi/lo ----
#pragma unroll
        for (int i = 0; i < 8; i++) {
            int f   = tid + 256 * i;       // float4 index 0..2047
            int row = f >> 4, c4 = f & 15;
            int gr  = row0 + row;
            float4 v = (gr < N_NODES)
                ? *(const float4*)&X[(long)gr * IN_CH + kc + c4 * 4]
                : make_float4(0.f, 0.f, 0.f, 0.f);
            float xv[4] = {v.x, v.y, v.z, v.w};
            uint32_t hi[2], lo[2];
#pragma unroll
            for (int q = 0; q < 2; q++) {
                __nv_bfloat16 h0 = __float2bfloat16(xv[2 * q]);
                __nv_bfloat16 h1 = __float2bfloat16(xv[2 * q + 1]);
                __nv_bfloat16 l0 = __float2bfloat16(xv[2 * q] - __bfloat162float(h0));
                __nv_bfloat16 l1 = __float2bfloat16(xv[2 * q + 1] - __bfloat162float(h1));
                hi[q] = (uint32_t)__bfloat16_as_ushort(h0) |
                        ((uint32_t)__bfloat16_as_ushort(h1) << 16);
                lo[q] = (uint32_t)__bfloat16_as_ushort(l0) |
                        ((uint32_t)__bfloat16_as_ushort(l1) << 16);
            }
            uint32_t off = (row * AST + c4 * 4) * 2;
            *(uint2*)(smem + SM_A_HI + off) = make_uint2(hi[0], hi[1]);
            *(uint2*)(smem + SM_A_LO + off) = make_uint2(lo[0], lo[1]);
        }

        // ---- B: [256 x 64] bf16 hi/lo (rows 0-127 W, 128-255 G) ----
        // 256 rows x 64 bf16 = 2048 16B-units; 8 units per row.
#pragma unroll
        for (int i = 0; i < 8; i++) {
            int u  = tid + 256 * i;        // 16B-unit 0..2047
            int n  = u >> 3, cu = u & 7;   // row 0..255, unit-in-row 0..7
            const __nv_bfloat16* sh = (n < 128) ? (g_wt_hi + n * IN_CH)
                                                : (g_gt_hi + (n - 128) * IN_CH);
            const __nv_bfloat16* sl = (n < 128) ? (g_wt_lo + n * IN_CH)
                                                : (g_gt_lo + (n - 128) * IN_CH);
            uint32_t off = (n * AST + cu * 8) * 2;
            *(uint4*)(smem + SM_B_HI + off) = *(const uint4*)(sh + kc + cu * 8);
            *(uint4*)(smem + SM_B_LO + off) = *(const uint4*)(sl + kc + cu * 8);
        }
        __syncthreads();

        // ---- compute: 4 k16 steps, 3 split passes each ----
#pragma unroll
        for (int ks = 0; ks < 4; ks++) {
            uint32_t ah[4][4], bh[8][2], bl[8][2], al[4][4];
#pragma unroll
            for (int mf = 0; mf < 4; mf++) {
                uint32_t ad = sb + SM_A_HI +
                    ((wm * 64 + mf * 16 + a_r) * AST + ks * 16 + a_c) * 2;
                ldsm_x4(ah[mf], ad);
            }
#pragma unroll
            for (int n2 = 0; n2 < 4; n2++) {
                uint32_t bd = sb + SM_B_HI +
                    ((wn * 64 + n2 * 16 + b_r) * AST + ks * 16 + b_c) * 2;
                uint32_t r[4];
                ldsm_x4(r, bd);
                bh[2 * n2][0] = r[0]; bh[2 * n2][1] = r[1];
                bh[2 * n2 + 1][0] = r[2]; bh[2 * n2 + 1][1] = r[3];
            }
#pragma unroll
            for (int mf = 0; mf < 4; mf++)
#pragma unroll
                for (int nf = 0; nf < 8; nf++)
                    mma16816(acc[mf][nf], ah[mf], bh[nf]);

#pragma unroll
            for (int n2 = 0; n2 < 4; n2++) {
                uint32_t bd = sb + SM_B_LO +
                    ((wn * 64 + n2 * 16 + b_r) * AST + ks * 16 + b_c) * 2;
                uint32_t r[4];
                ldsm_x4(r, bd);
                bl[2 * n2][0] = r[0]; bl[2 * n2][1] = r[1];
                bl[2 * n2 + 1][0] = r[2]; bl[2 * n2 + 1][1] = r[3];
            }
#pragma unroll
            for (int mf = 0; mf < 4; mf++)
#pragma unroll
                for (int nf = 0; nf < 8; nf++)
                    mma16816(acc[mf][nf], ah[mf], bl[nf]);

#pragma unroll
            for (int mf = 0; mf < 4; mf++) {
                uint32_t ad = sb + SM_A_LO +
                    ((wm * 64 + mf * 16 + a_r) * AST + ks * 16 + a_c) * 2;
                ldsm_x4(al[mf], ad);
            }
#pragma unroll
            for (int mf = 0; mf < 4; mf++)
#pragma unroll
                for (int nf = 0; nf < 8; nf++)
                    mma16816(acc[mf][nf], al[mf], bh[nf]);
        }
    }

    // ---- epilogue ----
    const int tr = lane >> 2;        // 0..7
    const int tc = (lane & 3) * 2;   // 0,2,4,6
#pragma unroll
    for (int mf = 0; mf < 4; mf++) {
#pragma unroll
        for (int nf = 0; nf < 8; nf++) {
            int gc = wn * 64 + nf * 8 + tc;             // 0..255
            float* dst = (gc < 128) ? g_support : g_gate;
            int col = gc & 127;
            int r0 = row0 + wm * 64 + mf * 16 + tr;
            if (r0 < N_NODES)
                *(float2*)&dst[(long)r0 * OUT_CH + col] =
                    make_float2(acc[mf][nf][0], acc[mf][nf][1]);
            int r1 = r0 + 8;
            if (r1 < N_NODES)
                *(float2*)&dst[(long)r1 * OUT_CH + col] =
                    make_float2(acc[mf][nf][2], acc[mf][nf][3]);
        }
    }
}

// ---------------- CSR build ------------------------------------------------
__global__ void zero_counts_kernel() {
    int i = blockIdx.x * blockDim.x + threadIdx.x;
    if (i < N_NODES) g_counts[i] = 0;
}

__global__ void hist_kernel(const void* __restrict__ rows) {
    int i = blockIdx.x * blockDim.x + threadIdx.x;
    if (i < N_EDGES) {
        int r = load_idx(rows, i, g_is64);
        if ((unsigned)r < (unsigned)N_NODES)
            atomicAdd(&g_counts[r], 1);
    }
}

__global__ __launch_bounds__(1024) void scan_kernel() {
    __shared__ int s_warp[32];
    __shared__ int s_total;
    const int tid = threadIdx.x, lane = tid & 31, wid = tid >> 5;
    int carry = 0;
    for (int base = 0; base < N_NODES; base += 1024) {
        int i = base + tid;
        int v = (i < N_NODES) ? g_counts[i] : 0;
        int sum = v;
#pragma unroll
        for (int off = 1; off < 32; off <<= 1) {
            int n = __shfl_up_sync(0xffffffffu, sum, off);
            if (lane >= off) sum += n;
        }
        if (lane == 31) s_warp[wid] = sum;
        __syncthreads();
        if (wid == 0) {
            int w = s_warp[lane];
            int iw = w;
#pragma unroll
            for (int off = 1; off < 32; off <<= 1) {
                int n = __shfl_up_sync(0xffffffffu, iw, off);
                if (lane >= off) iw += n;
            }
            s_warp[lane] = iw - w;
            if (lane == 31) s_total = iw;
        }
        __syncthreads();
        int excl = carry + s_warp[wid] + (sum - v);
        if (i < N_NODES) { g_row_ptr[i] = excl; g_cursor[i] = excl; }
        carry += s_total;
        __syncthreads();
    }
    if (tid == 0) g_row_ptr[N_NODES] = carry;
}

__global__ void scatter_kernel(const void* __restrict__ rows,
                               const void* __restrict__ cols,
                               const float* __restrict__ vals) {
    int i = blockIdx.x * blockDim.x + threadIdx.x;
    if (i < N_EDGES) {
        int is64 = g_is64;
        int r = load_idx(rows, i, is64);
        int c = load_idx(cols, i, is64);
        if ((unsigned)r >= (unsigned)N_NODES) return;
        int p = atomicAdd(&g_cursor[r], 1);
        if ((unsigned)p < (unsigned)N_EDGES)
            g_pairs[p] = make_int2(c, __float_as_int(vals[i]));
    }
}

// ---------------- gather SpMM + gating -------------------------------------
__global__ __launch_bounds__(256) void spmm_kernel(float* __restrict__ out) {
    int warp_id = (blockIdx.x * blockDim.x + threadIdx.x) >> 5;
    int lane = threadIdx.x & 31;
    if (warp_id >= N_NODES) return;
    int s = g_row_ptr[warp_id];
    int e = g_row_ptr[warp_id + 1];
    int c4 = lane * 4;
    float4 aS = make_float4(0.f, 0.f, 0.f, 0.f);
    float4 aG = make_float4(0.f, 0.f, 0.f, 0.f);

    int2 np = make_int2(0, 0);
    if (s < e) np = g_pairs[s];
#pragma unroll 2
    for (int i = s; i < e; i++) {
        int   c = np.x;
        float v = __int_as_float(np.y);
        if (i + 1 < e) np = g_pairs[i + 1];
        float4 sv = *(const float4*)&g_support[(long)c * OUT_CH + c4];
        float4 gv = *(const float4*)&g_gate[(long)c * OUT_CH + c4];
        aS.x += v * sv.x; aS.y += v * sv.y; aS.z += v * sv.z; aS.w += v * sv.w;
        aG.x += v * gv.x; aG.y += v * gv.y; aG.z += v * gv.z; aG.w += v * gv.w;
    }
    float4 o;
    o.x = aS.x / (1.0f + __expf(-aG.x));
    o.y = aS.y / (1.0f + __expf(-aG.y));
    o.z = aS.z / (1.0f + __expf(-aG.z));
    o.w = aS.w / (1.0f + __expf(-aG.w));
    *(float4*)&out[(long)warp_id * OUT_CH + c4] = o;
}

// ---------------- launch ----------------------------------------------------
extern "C" void kernel_launch(void* const* d_in, const int* in_sizes, int n_in,
                              void* d_out, int out_size) {
    const float* x   = (const float*)d_in[0];
    const void*  er  = d_in[1];
    const void*  ec  = d_in[2];
    const float* ev  = (const float*)d_in[3];
    const float* w   = (const float*)d_in[4];
    const float* gw  = (const float*)d_in[5];
    float* out = (float*)d_out;

    cudaFuncSetAttribute(gemm_mma_kernel,
                         cudaFuncAttributeMaxDynamicSharedMemorySize, GEMM_SMEM);

    detect_kernel<<<1, 32>>>((const unsigned int*)er);
    prep_w_kernel<<<(IN_CH * OUT_CH + 255) / 256, 256>>>(w, gw);
    gemm_mma_kernel<<<(N_NODES + 127) / 128, 256, GEMM_SMEM>>>(x);
    zero_counts_kernel<<<(N_NODES + 255) / 256, 256>>>();
    hist_kernel<<<(N_EDGES + 255) / 256, 256>>>(er);
    scan_kernel<<<1, 1024>>>();
    scatter_kernel<<<(N_EDGES + 255) / 256, 256>>>(er, ec, ev);
    spmm_kernel<<<(N_NODES * 32 + 255) / 256, 256>>>(out);
}

// round 10
// speedup vs baseline: 1.4998x; 1.0874x over previous
#include <cuda_runtime.h>
#include <cuda_bf16.h>
#include <cstdint>

#define N_NODES 50000
#define N_EDGES 800000
#define IN_CH   256
#define OUT_CH  128

// ---------------- scratch (device globals; no allocation allowed) -----------
__device__ __align__(128) float g_support[N_NODES * OUT_CH];
__device__ __align__(128) float g_gate[N_NODES * OUT_CH];
__device__ __align__(16) int   g_counts[N_NODES];
__device__ __align__(16) int   g_cursor[N_NODES];
__device__ __align__(16) int   g_row_ptr[N_NODES + 4];
__device__ __align__(128) int2 g_pairs[N_EDGES];  // (col, val-as-int)
__device__ int   g_is64;
// W/G transposed [N=128, K=256] bf16 hi/lo splits
__device__ __align__(128) __nv_bfloat16 g_wt_hi[OUT_CH * IN_CH];
__device__ __align__(128) __nv_bfloat16 g_wt_lo[OUT_CH * IN_CH];
__device__ __align__(128) __nv_bfloat16 g_gt_hi[OUT_CH * IN_CH];
__device__ __align__(128) __nv_bfloat16 g_gt_lo[OUT_CH * IN_CH];

// ---------------- helpers ----------------------------------------------------
__device__ __forceinline__ uint32_t smem_u32(const void* p) {
    uint32_t a;
    asm("{ .reg .u64 t; cvta.to.shared.u64 t, %1; cvt.u32.u64 %0, t; }"
        : "=r"(a) : "l"(p));
    return a;
}

__device__ __forceinline__ void ldsm_x4(uint32_t* r, uint32_t addr) {
    asm volatile("ldmatrix.sync.aligned.m8n8.x4.shared.b16 {%0,%1,%2,%3}, [%4];"
                 : "=r"(r[0]), "=r"(r[1]), "=r"(r[2]), "=r"(r[3]) : "r"(addr));
}

__device__ __forceinline__ void mma16816(float* c, const uint32_t* a, const uint32_t* b) {
    asm volatile(
        "mma.sync.aligned.m16n8k16.row.col.f32.bf16.bf16.f32 "
        "{%0,%1,%2,%3}, {%4,%5,%6,%7}, {%8,%9}, {%0,%1,%2,%3};"
        : "+f"(c[0]), "+f"(c[1]), "+f"(c[2]), "+f"(c[3])
        : "r"(a[0]), "r"(a[1]), "r"(a[2]), "r"(a[3]), "r"(b[0]), "r"(b[1]));
}

// Decode edge index of unknown (int32 vs int64) dtype.
__device__ __forceinline__ int load_idx(const void* p, int i, int is64) {
    if (is64) return (int)((const long long*)p)[i];
    return ((const int*)p)[i];
}

// ---------------- zero counts + dtype detect (merged) ------------------------
__global__ void zero_detect_kernel(const unsigned int* __restrict__ rows_u32) {
    int i = blockIdx.x * blockDim.x + threadIdx.x;
    if (i < N_NODES) g_counts[i] = 0;
    if (i == 0) {
        int all_zero = 1;
        for (int j = 0; j < 64; j++)
            if (rows_u32[2 * j + 1] != 0u) { all_zero = 0; break; }
        g_is64 = all_zero;
    }
}

// ---------------- W/G prep: transpose + bf16 hi/lo split ---------------------
__global__ void prep_w_kernel(const float* __restrict__ W, const float* __restrict__ G) {
    int i = blockIdx.x * blockDim.x + threadIdx.x;
    if (i >= IN_CH * OUT_CH) return;
    int k = i >> 7;    // 0..255
    int n = i & 127;   // 0..127
    float w = W[i];
    __nv_bfloat16 wh = __float2bfloat16(w);
    __nv_bfloat16 wl = __float2bfloat16(w - __bfloat162float(wh));
    g_wt_hi[n * IN_CH + k] = wh;
    g_wt_lo[n * IN_CH + k] = wl;
    float g = G[i];
    __nv_bfloat16 gh = __float2bfloat16(g);
    __nv_bfloat16 gl = __float2bfloat16(g - __bfloat162float(gh));
    g_gt_hi[n * IN_CH + k] = gh;
    g_gt_lo[n * IN_CH + k] = gl;
}

// ---------------- mma.sync dual GEMM (bf16x3 split) -------------------------
// CTA: 128 rows x 256 cols (cols 0-127 -> support, 128-255 -> gate).
// 8 warps in 2(m) x 4(n) grid; warp tile 64x64; mma.m16n8k16 bf16.
#define KC        64
#define NCHUNK    (IN_CH / KC)   // 4
#define AST       72             // smem stride (elems) for 64-col tiles
#define SM_A_HI   0
#define SM_A_LO   (128 * AST * 2)            // 18432
#define SM_B_HI   (2 * 128 * AST * 2)        // 36864
#define SM_B_LO   (SM_B_HI + 256 * AST * 2)  // 73728
#define GEMM_SMEM (SM_B_LO + 256 * AST * 2)  // 110592

__global__ __launch_bounds__(256) void gemm_mma_kernel(const float* __restrict__ X) {
    extern __shared__ char smem[];
    const uint32_t sb = smem_u32(smem);
    const int tid  = threadIdx.x;
    const int wid  = tid >> 5;
    const int lane = tid & 31;
    const int wm   = wid & 1;    // m-tile 0..1 (64 rows each)
    const int wn   = wid >> 1;   // n-tile 0..3 (64 cols each)
    const int row0 = blockIdx.x * 128;

    float acc[4][8][4];
#pragma unroll
    for (int mf = 0; mf < 4; mf++)
#pragma unroll
        for (int nf = 0; nf < 8; nf++)
#pragma unroll
            for (int q = 0; q < 4; q++) acc[mf][nf][q] = 0.f;

    // ldmatrix lane addresses (element offsets; x2 bytes at use)
    const int a_r = lane & 15, a_c = (lane >> 4) << 3;          // A: 16x16 quads
    const int b_q = lane >> 3;                                   // B: quad id
    const int b_r = ((b_q >> 1) << 3) + (lane & 7);              // n offset
    const int b_c = (b_q & 1) << 3;                              // k offset

    for (int c = 0; c < NCHUNK; c++) {
        const int kc = c * KC;
        __syncthreads();  // previous chunk's compute done before overwrite

        // ---- A: 128x64 fp32 -> bf16 hi/lo ----
#pragma unroll
        for (int i = 0; i < 8; i++) {
            int f   = tid + 256 * i;       // float4 index 0..2047
            int row = f >> 4, c4 = f & 15;
            int gr  = row0 + row;
            float4 v = (gr < N_NODES)
                ? *(const float4*)&X[(long)gr * IN_CH + kc + c4 * 4]
                : make_float4(0.f, 0.f, 0.f, 0.f);
            float xv[4] = {v.x, v.y, v.z, v.w};
            uint32_t hi[2], lo[2];
#pragma unroll
            for (int q = 0; q < 2; q++) {
                __nv_bfloat16 h0 = __float2bfloat16(xv[2 * q]);
                __nv_bfloat16 h1 = __float2bfloat16(xv[2 * q + 1]);
                __nv_bfloat16 l0 = __float2bfloat16(xv[2 * q] - __bfloat162float(h0));
                __nv_bfloat16 l1 = __float2bfloat16(xv[2 * q + 1] - __bfloat162float(h1));
                hi[q] = (uint32_t)__bfloat16_as_ushort(h0) |
                        ((uint32_t)__bfloat16_as_ushort(h1) << 16);
                lo[q] = (uint32_t)__bfloat16_as_ushort(l0) |
                        ((uint32_t)__bfloat16_as_ushort(l1) << 16);
            }
            uint32_t off = (row * AST + c4 * 4) * 2;
            *(uint2*)(smem + SM_A_HI + off) = make_uint2(hi[0], hi[1]);
            *(uint2*)(smem + SM_A_LO + off) = make_uint2(lo[0], lo[1]);
        }

        // ---- B: [256 x 64] bf16 hi/lo (rows 0-127 W, 128-255 G) ----
        // 256 rows x 64 bf16 = 2048 16B-units; 8 units per row.
#pragma unroll
        for (int i = 0; i < 8; i++) {
            int u  = tid + 256 * i;        // 16B-unit 0..2047
            int n  = u >> 3, cu = u & 7;   // row 0..255, unit-in-row 0..7
            const __nv_bfloat16* sh = (n < 128) ? (g_wt_hi + n * IN_CH)
                                                : (g_gt_hi + (n - 128) * IN_CH);
            const __nv_bfloat16* sl = (n < 128) ? (g_wt_lo + n * IN_CH)
                                                : (g_gt_lo + (n - 128) * IN_CH);
            uint32_t off = (n * AST + cu * 8) * 2;
            *(uint4*)(smem + SM_B_HI + off) = *(const uint4*)(sh + kc + cu * 8);
            *(uint4*)(smem + SM_B_LO + off) = *(const uint4*)(sl + kc + cu * 8);
        }
        __syncthreads();

        // ---- compute: 4 k16 steps, 3 split passes each ----
#pragma unroll
        for (int ks = 0; ks < 4; ks++) {
            uint32_t ah[4][4], bh[8][2], bl[8][2], al[4][4];
#pragma unroll
            for (int mf = 0; mf < 4; mf++) {
                uint32_t ad = sb + SM_A_HI +
                    ((wm * 64 + mf * 16 + a_r) * AST + ks * 16 + a_c) * 2;
                ldsm_x4(ah[mf], ad);
            }
#pragma unroll
            for (int n2 = 0; n2 < 4; n2++) {
                uint32_t bd = sb + SM_B_HI +
                    ((wn * 64 + n2 * 16 + b_r) * AST + ks * 16 + b_c) * 2;
                uint32_t r[4];
                ldsm_x4(r, bd);
                bh[2 * n2][0] = r[0]; bh[2 * n2][1] = r[1];
                bh[2 * n2 + 1][0] = r[2]; bh[2 * n2 + 1][1] = r[3];
            }
#pragma unroll
            for (int mf = 0; mf < 4; mf++)
#pragma unroll
                for (int nf = 0; nf < 8; nf++)
                    mma16816(acc[mf][nf], ah[mf], bh[nf]);

#pragma unroll
            for (int n2 = 0; n2 < 4; n2++) {
                uint32_t bd = sb + SM_B_LO +
                    ((wn * 64 + n2 * 16 + b_r) * AST + ks * 16 + b_c) * 2;
                uint32_t r[4];
                ldsm_x4(r, bd);
                bl[2 * n2][0] = r[0]; bl[2 * n2][1] = r[1];
                bl[2 * n2 + 1][0] = r[2]; bl[2 * n2 + 1][1] = r[3];
            }
#pragma unroll
            for (int mf = 0; mf < 4; mf++)
#pragma unroll
                for (int nf = 0; nf < 8; nf++)
                    mma16816(acc[mf][nf], ah[mf], bl[nf]);

#pragma unroll
            for (int mf = 0; mf < 4; mf++) {
                uint32_t ad = sb + SM_A_LO +
                    ((wm * 64 + mf * 16 + a_r) * AST + ks * 16 + a_c) * 2;
                ldsm_x4(al[mf], ad);
            }
#pragma unroll
            for (int mf = 0; mf < 4; mf++)
#pragma unroll
                for (int nf = 0; nf < 8; nf++)
                    mma16816(acc[mf][nf], al[mf], bh[nf]);
        }
    }

    // ---- epilogue ----
    const int tr = lane >> 2;        // 0..7
    const int tc = (lane & 3) * 2;   // 0,2,4,6
#pragma unroll
    for (int mf = 0; mf < 4; mf++) {
#pragma unroll
        for (int nf = 0; nf < 8; nf++) {
            int gc = wn * 64 + nf * 8 + tc;             // 0..255
            float* dst = (gc < 128) ? g_support : g_gate;
            int col = gc & 127;
            int r0 = row0 + wm * 64 + mf * 16 + tr;
            if (r0 < N_NODES)
                *(float2*)&dst[(long)r0 * OUT_CH + col] =
                    make_float2(acc[mf][nf][0], acc[mf][nf][1]);
            int r1 = r0 + 8;
            if (r1 < N_NODES)
                *(float2*)&dst[(long)r1 * OUT_CH + col] =
                    make_float2(acc[mf][nf][2], acc[mf][nf][3]);
        }
    }
}

// ---------------- CSR build ------------------------------------------------
__global__ void hist_kernel(const void* __restrict__ rows) {
    int i = blockIdx.x * blockDim.x + threadIdx.x;
    if (i < N_EDGES) {
        int r = load_idx(rows, i, g_is64);
        if ((unsigned)r < (unsigned)N_NODES)
            atomicAdd(&g_counts[r], 1);
    }
}

// Single-block exclusive scan; 4 elements/thread via int4 (13 iterations).
#define SCAN_I4 (N_NODES / 4)     // 12500 int4 chunks (N_NODES % 4 == 0)
__global__ __launch_bounds__(1024) void scan_kernel() {
    __shared__ int s_warp[32];
    __shared__ int s_total;
    const int tid = threadIdx.x, lane = tid & 31, wid = tid >> 5;
    int carry = 0;
    for (int base = 0; base < SCAN_I4; base += 1024) {
        int i4 = base + tid;
        int4 v = (i4 < SCAN_I4) ? ((const int4*)g_counts)[i4]
                                : make_int4(0, 0, 0, 0);
        int t = v.x + v.y + v.z + v.w;
        int sum = t;
#pragma unroll
        for (int off = 1; off < 32; off <<= 1) {
            int n = __shfl_up_sync(0xffffffffu, sum, off);
            if (lane >= off) sum += n;
        }
        if (lane == 31) s_warp[wid] = sum;
        __syncthreads();
        if (wid == 0) {
            int w = s_warp[lane];
            int iw = w;
#pragma unroll
            for (int off = 1; off < 32; off <<= 1) {
                int n = __shfl_up_sync(0xffffffffu, iw, off);
                if (lane >= off) iw += n;
            }
            s_warp[lane] = iw - w;  // exclusive warp offsets
            if (lane == 31) s_total = iw;
        }
        __syncthreads();
        if (i4 < SCAN_I4) {
            int e0 = carry + s_warp[wid] + (sum - t);
            int4 ex = make_int4(e0, e0 + v.x, e0 + v.x + v.y, e0 + v.x + v.y + v.z);
            ((int4*)g_row_ptr)[i4] = ex;
            ((int4*)g_cursor)[i4]  = ex;
        }
        carry += s_total;
        __syncthreads();  // protect s_warp/s_total for next chunk
    }
    if (tid == 0) g_row_ptr[N_NODES] = carry;
}

__global__ void scatter_kernel(const void* __restrict__ rows,
                               const void* __restrict__ cols,
                               const float* __restrict__ vals) {
    int i = blockIdx.x * blockDim.x + threadIdx.x;
    if (i < N_EDGES) {
        int is64 = g_is64;
        int r = load_idx(rows, i, is64);
        int c = load_idx(cols, i, is64);
        if ((unsigned)r >= (unsigned)N_NODES) return;
        int p = atomicAdd(&g_cursor[r], 1);
        if ((unsigned)p < (unsigned)N_EDGES)
            g_pairs[p] = make_int2(c, __float_as_int(vals[i]));
    }
}

// ---------------- gather SpMM + gating -------------------------------------
// One warp per output row; lane handles 4 channels (float4).
// 4-deep edge pipeline: 8 gathers + 4 next-pair loads in flight per warp.
__global__ __launch_bounds__(256) void spmm_kernel(float* __restrict__ out) {
    int warp_id = (blockIdx.x * blockDim.x + threadIdx.x) >> 5;
    int lane = threadIdx.x & 31;
    if (warp_id >= N_NODES) return;
    int s = g_row_ptr[warp_id];
    int e = g_row_ptr[warp_id + 1];
    const float* supB = g_support + lane * 4;
    const float* gatB = g_gate + lane * 4;
    float4 aS = make_float4(0.f, 0.f, 0.f, 0.f);
    float4 aG = make_float4(0.f, 0.f, 0.f, 0.f);

    int i = s;
    int2 p0, p1, p2, p3;
    if (i + 4 <= e) {
        p0 = g_pairs[i]; p1 = g_pairs[i + 1];
        p2 = g_pairs[i + 2]; p3 = g_pairs[i + 3];
    }
    while (i + 4 <= e) {
        int2 q0 = p0, q1 = p1, q2 = p2, q3 = p3;
        int j = i + 4;
        if (j + 4 <= e) {
            p0 = g_pairs[j]; p1 = g_pairs[j + 1];
            p2 = g_pairs[j + 2]; p3 = g_pairs[j + 3];
        }
        float4 s0 = *(const float4*)(supB + (long)q0.x * OUT_CH);
        float4 g0 = *(const float4*)(gatB + (long)q0.x * OUT_CH);
        float4 s1 = *(const float4*)(supB + (long)q1.x * OUT_CH);
        float4 g1 = *(const float4*)(gatB + (long)q1.x * OUT_CH);
        float4 s2 = *(const float4*)(supB + (long)q2.x * OUT_CH);
        float4 g2 = *(const float4*)(gatB + (long)q2.x * OUT_CH);
        float4 s3 = *(const float4*)(supB + (long)q3.x * OUT_CH);
        float4 g3 = *(const float4*)(gatB + (long)q3.x * OUT_CH);
        float v0 = __int_as_float(q0.y), v1 = __int_as_float(q1.y);
        float v2 = __int_as_float(q2.y), v3 = __int_as_float(q3.y);
        aS.x += v0 * s0.x; aS.y += v0 * s0.y; aS.z += v0 * s0.z; aS.w += v0 * s0.w;
        aG.x += v0 * g0.x; aG.y += v0 * g0.y; aG.z += v0 * g0.z; aG.w += v0 * g0.w;
        aS.x += v1 * s1.x; aS.y += v1 * s1.y; aS.z += v1 * s1.z; aS.w += v1 * s1.w;
        aG.x += v1 * g1.x; aG.y += v1 * g1.y; aG.z += v1 * g1.z; aG.w += v1 * g1.w;
        aS.x += v2 * s2.x; aS.y += v2 * s2.y; aS.z += v2 * s2.z; aS.w += v2 * s2.w;
        aG.x += v2 * g2.x; aG.y += v2 * g2.y; aG.z += v2 * g2.z; aG.w += v2 * g2.w;
        aS.x += v3 * s3.x; aS.y += v3 * s3.y; aS.z += v3 * s3.z; aS.w += v3 * s3.w;
        aG.x += v3 * g3.x; aG.y += v3 * g3.y; aG.z += v3 * g3.z; aG.w += v3 * g3.w;
        i = j;
    }
    for (; i < e; i++) {
        int2 q = g_pairs[i];
        float v = __int_as_float(q.y);
        float4 sv = *(const float4*)(supB + (long)q.x * OUT_CH);
        float4 gv = *(const float4*)(gatB + (long)q.x * OUT_CH);
        aS.x += v * sv.x; aS.y += v * sv.y; aS.z += v * sv.z; aS.w += v * sv.w;
        aG.x += v * gv.x; aG.y += v * gv.y; aG.z += v * gv.z; aG.w += v * gv.w;
    }
    float4 o;
    o.x = aS.x / (1.0f + __expf(-aG.x));
    o.y = aS.y / (1.0f + __expf(-aG.y));
    o.z = aS.z / (1.0f + __expf(-aG.z));
    o.w = aS.w / (1.0f + __expf(-aG.w));
    *(float4*)&out[(long)warp_id * OUT_CH + lane * 4] = o;
}

// ---------------- launch ----------------------------------------------------
extern "C" void kernel_launch(void* const* d_in, const int* in_sizes, int n_in,
                              void* d_out, int out_size) {
    const float* x   = (const float*)d_in[0];
    const void*  er  = d_in[1];
    const void*  ec  = d_in[2];
    const float* ev  = (const float*)d_in[3];
    const float* w   = (const float*)d_in[4];
    const float* gw  = (const float*)d_in[5];
    float* out = (float*)d_out;

    cudaFuncSetAttribute(gemm_mma_kernel,
                         cudaFuncAttributeMaxDynamicSharedMemorySize, GEMM_SMEM);

    zero_detect_kernel<<<(N_NODES + 255) / 256, 256>>>((const unsigned int*)er);
    prep_w_kernel<<<(IN_CH * OUT_CH + 255) / 256, 256>>>(w, gw);
    gemm_mma_kernel<<<(N_NODES + 127) / 128, 256, GEMM_SMEM>>>(x);
    hist_kernel<<<(N_EDGES + 255) / 256, 256>>>(er);
    scan_kernel<<<1, 1024>>>();
    scatter_kernel<<<(N_EDGES + 255) / 256, 256>>>(er, ec, ev);
    spmm_kernel<<<(N_NODES * 32 + 255) / 256, 256>>>(out);
}

// round 11
// speedup vs baseline: 1.7085x; 1.1392x over previous
#include <cuda_runtime.h>
#include <cuda_bf16.h>
#include <cstdint>

#define N_NODES 50000
#define N_EDGES 800000
#define IN_CH   256
#define OUT_CH  128

// ---------------- scratch (device globals; no allocation allowed) -----------
__device__ __align__(128) float g_support[N_NODES * OUT_CH];
__device__ __align__(128) float g_gate[N_NODES * OUT_CH];
__device__ __align__(16) int   g_counts[N_NODES];
__device__ __align__(16) int   g_cursor[N_NODES];
__device__ __align__(16) int   g_row_ptr[N_NODES + 4];
__device__ __align__(128) int2 g_pairs[N_EDGES];  // (col, val-as-int)
__device__ int   g_is64;
// W/G transposed [N=128, K=256] bf16 hi/lo splits
__device__ __align__(128) __nv_bfloat16 g_wt_hi[OUT_CH * IN_CH];
__device__ __align__(128) __nv_bfloat16 g_wt_lo[OUT_CH * IN_CH];
__device__ __align__(128) __nv_bfloat16 g_gt_hi[OUT_CH * IN_CH];
__device__ __align__(128) __nv_bfloat16 g_gt_lo[OUT_CH * IN_CH];

// ---------------- helpers ----------------------------------------------------
__device__ __forceinline__ uint32_t smem_u32(const void* p) {
    uint32_t a;
    asm("{ .reg .u64 t; cvta.to.shared.u64 t, %1; cvt.u32.u64 %0, t; }"
        : "=r"(a) : "l"(p));
    return a;
}

__device__ __forceinline__ void ldsm_x4(uint32_t* r, uint32_t addr) {
    asm volatile("ldmatrix.sync.aligned.m8n8.x4.shared.b16 {%0,%1,%2,%3}, [%4];"
                 : "=r"(r[0]), "=r"(r[1]), "=r"(r[2]), "=r"(r[3]) : "r"(addr));
}

__device__ __forceinline__ void mma16816(float* c, const uint32_t* a, const uint32_t* b) {
    asm volatile(
        "mma.sync.aligned.m16n8k16.row.col.f32.bf16.bf16.f32 "
        "{%0,%1,%2,%3}, {%4,%5,%6,%7}, {%8,%9}, {%0,%1,%2,%3};"
        : "+f"(c[0]), "+f"(c[1]), "+f"(c[2]), "+f"(c[3])
        : "r"(a[0]), "r"(a[1]), "r"(a[2]), "r"(a[3]), "r"(b[0]), "r"(b[1]));
}

// Decode edge index of unknown (int32 vs int64) dtype.
__device__ __forceinline__ int load_idx(const void* p, int i, int is64) {
    if (is64) return (int)((const long long*)p)[i];
    return ((const int*)p)[i];
}

// ---------------- zero counts + dtype detect (merged) ------------------------
__global__ void zero_detect_kernel(const unsigned int* __restrict__ rows_u32) {
    int i = blockIdx.x * blockDim.x + threadIdx.x;
    if (i < N_NODES) g_counts[i] = 0;
    if (i == 0) {
        int all_zero = 1;
        for (int j = 0; j < 64; j++)
            if (rows_u32[2 * j + 1] != 0u) { all_zero = 0; break; }
        g_is64 = all_zero;
    }
}

// ---------------- W/G prep: transpose + bf16 hi/lo split ---------------------
__global__ void prep_w_kernel(const float* __restrict__ W, const float* __restrict__ G) {
    int i = blockIdx.x * blockDim.x + threadIdx.x;
    if (i >= IN_CH * OUT_CH) return;
    int k = i >> 7;    // 0..255
    int n = i & 127;   // 0..127
    float w = W[i];
    __nv_bfloat16 wh = __float2bfloat16(w);
    __nv_bfloat16 wl = __float2bfloat16(w - __bfloat162float(wh));
    g_wt_hi[n * IN_CH + k] = wh;
    g_wt_lo[n * IN_CH + k] = wl;
    float g = G[i];
    __nv_bfloat16 gh = __float2bfloat16(g);
    __nv_bfloat16 gl = __float2bfloat16(g - __bfloat162float(gh));
    g_gt_hi[n * IN_CH + k] = gh;
    g_gt_lo[n * IN_CH + k] = gl;
}

// ---------------- mma.sync dual GEMM (bf16x3 split) -------------------------
// CTA: 128 rows x 256 cols (cols 0-127 -> support, 128-255 -> gate).
// 8 warps in 2(m) x 4(n) grid; warp tile 64x64; mma.m16n8k16 bf16.
#define KC        64
#define NCHUNK    (IN_CH / KC)   // 4
#define AST       72             // smem stride (elems) for 64-col tiles
#define SM_A_HI   0
#define SM_A_LO   (128 * AST * 2)            // 18432
#define SM_B_HI   (2 * 128 * AST * 2)        // 36864
#define SM_B_LO   (SM_B_HI + 256 * AST * 2)  // 73728
#define GEMM_SMEM (SM_B_LO + 256 * AST * 2)  // 110592

__global__ __launch_bounds__(256) void gemm_mma_kernel(const float* __restrict__ X) {
    extern __shared__ char smem[];
    const uint32_t sb = smem_u32(smem);
    const int tid  = threadIdx.x;
    const int wid  = tid >> 5;
    const int lane = tid & 31;
    const int wm   = wid & 1;    // m-tile 0..1 (64 rows each)
    const int wn   = wid >> 1;   // n-tile 0..3 (64 cols each)
    const int row0 = blockIdx.x * 128;

    float acc[4][8][4];
#pragma unroll
    for (int mf = 0; mf < 4; mf++)
#pragma unroll
        for (int nf = 0; nf < 8; nf++)
#pragma unroll
            for (int q = 0; q < 4; q++) acc[mf][nf][q] = 0.f;

    // ldmatrix lane addresses (element offsets; x2 bytes at use)
    const int a_r = lane & 15, a_c = (lane >> 4) << 3;          // A: 16x16 quads
    const int b_q = lane >> 3;                                   // B: quad id
    const int b_r = ((b_q >> 1) << 3) + (lane & 7);              // n offset
    const int b_c = (b_q & 1) << 3;                              // k offset

    for (int c = 0; c < NCHUNK; c++) {
        const int kc = c * KC;
        __syncthreads();  // previous chunk's compute done before overwrite

        // ---- A: 128x64 fp32 -> bf16 hi/lo ----
#pragma unroll
        for (int i = 0; i < 8; i++) {
            int f   = tid + 256 * i;       // float4 index 0..2047
            int row = f >> 4, c4 = f & 15;
            int gr  = row0 + row;
            float4 v = (gr < N_NODES)
                ? *(const float4*)&X[(long)gr * IN_CH + kc + c4 * 4]
                : make_float4(0.f, 0.f, 0.f, 0.f);
            float xv[4] = {v.x, v.y, v.z, v.w};
            uint32_t hi[2], lo[2];
#pragma unroll
            for (int q = 0; q < 2; q++) {
                __nv_bfloat16 h0 = __float2bfloat16(xv[2 * q]);
                __nv_bfloat16 h1 = __float2bfloat16(xv[2 * q + 1]);
                __nv_bfloat16 l0 = __float2bfloat16(xv[2 * q] - __bfloat162float(h0));
                __nv_bfloat16 l1 = __float2bfloat16(xv[2 * q + 1] - __bfloat162float(h1));
                hi[q] = (uint32_t)__bfloat16_as_ushort(h0) |
                        ((uint32_t)__bfloat16_as_ushort(h1) << 16);
                lo[q] = (uint32_t)__bfloat16_as_ushort(l0) |
                        ((uint32_t)__bfloat16_as_ushort(l1) << 16);
            }
            uint32_t off = (row * AST + c4 * 4) * 2;
            *(uint2*)(smem + SM_A_HI + off) = make_uint2(hi[0], hi[1]);
            *(uint2*)(smem + SM_A_LO + off) = make_uint2(lo[0], lo[1]);
        }

        // ---- B: [256 x 64] bf16 hi/lo (rows 0-127 W, 128-255 G) ----
        // 256 rows x 64 bf16 = 2048 16B-units; 8 units per row.
#pragma unroll
        for (int i = 0; i < 8; i++) {
            int u  = tid + 256 * i;        // 16B-unit 0..2047
            int n  = u >> 3, cu = u & 7;   // row 0..255, unit-in-row 0..7
            const __nv_bfloat16* sh = (n < 128) ? (g_wt_hi + n * IN_CH)
                                                : (g_gt_hi + (n - 128) * IN_CH);
            const __nv_bfloat16* sl = (n < 128) ? (g_wt_lo + n * IN_CH)
                                                : (g_gt_lo + (n - 128) * IN_CH);
            uint32_t off = (n * AST + cu * 8) * 2;
            *(uint4*)(smem + SM_B_HI + off) = *(const uint4*)(sh + kc + cu * 8);
            *(uint4*)(smem + SM_B_LO + off) = *(const uint4*)(sl + kc + cu * 8);
        }
        __syncthreads();

        // ---- compute: 4 k16 steps, 3 split passes each ----
#pragma unroll
        for (int ks = 0; ks < 4; ks++) {
            uint32_t ah[4][4], bh[8][2], bl[8][2], al[4][4];
#pragma unroll
            for (int mf = 0; mf < 4; mf++) {
                uint32_t ad = sb + SM_A_HI +
                    ((wm * 64 + mf * 16 + a_r) * AST + ks * 16 + a_c) * 2;
                ldsm_x4(ah[mf], ad);
            }
#pragma unroll
            for (int n2 = 0; n2 < 4; n2++) {
                uint32_t bd = sb + SM_B_HI +
                    ((wn * 64 + n2 * 16 + b_r) * AST + ks * 16 + b_c) * 2;
                uint32_t r[4];
                ldsm_x4(r, bd);
                bh[2 * n2][0] = r[0]; bh[2 * n2][1] = r[1];
                bh[2 * n2 + 1][0] = r[2]; bh[2 * n2 + 1][1] = r[3];
            }
#pragma unroll
            for (int mf = 0; mf < 4; mf++)
#pragma unroll
                for (int nf = 0; nf < 8; nf++)
                    mma16816(acc[mf][nf], ah[mf], bh[nf]);

#pragma unroll
            for (int n2 = 0; n2 < 4; n2++) {
                uint32_t bd = sb + SM_B_LO +
                    ((wn * 64 + n2 * 16 + b_r) * AST + ks * 16 + b_c) * 2;
                uint32_t r[4];
                ldsm_x4(r, bd);
                bl[2 * n2][0] = r[0]; bl[2 * n2][1] = r[1];
                bl[2 * n2 + 1][0] = r[2]; bl[2 * n2 + 1][1] = r[3];
            }
#pragma unroll
            for (int mf = 0; mf < 4; mf++)
#pragma unroll
                for (int nf = 0; nf < 8; nf++)
                    mma16816(acc[mf][nf], ah[mf], bl[nf]);

#pragma unroll
            for (int mf = 0; mf < 4; mf++) {
                uint32_t ad = sb + SM_A_LO +
                    ((wm * 64 + mf * 16 + a_r) * AST + ks * 16 + a_c) * 2;
                ldsm_x4(al[mf], ad);
            }
#pragma unroll
            for (int mf = 0; mf < 4; mf++)
#pragma unroll
                for (int nf = 0; nf < 8; nf++)
                    mma16816(acc[mf][nf], al[mf], bh[nf]);
        }
    }

    // ---- epilogue ----
    const int tr = lane >> 2;        // 0..7
    const int tc = (lane & 3) * 2;   // 0,2,4,6
#pragma unroll
    for (int mf = 0; mf < 4; mf++) {
#pragma unroll
        for (int nf = 0; nf < 8; nf++) {
            int gc = wn * 64 + nf * 8 + tc;             // 0..255
            float* dst = (gc < 128) ? g_support : g_gate;
            int col = gc & 127;
            int r0 = row0 + wm * 64 + mf * 16 + tr;
            if (r0 < N_NODES)
                *(float2*)&dst[(long)r0 * OUT_CH + col] =
                    make_float2(acc[mf][nf][0], acc[mf][nf][1]);
            int r1 = r0 + 8;
            if (r1 < N_NODES)
                *(float2*)&dst[(long)r1 * OUT_CH + col] =
                    make_float2(acc[mf][nf][2], acc[mf][nf][3]);
        }
    }
}

// ---------------- CSR build ------------------------------------------------
// 4 edges per thread: independent index loads (MLP=4) + 4 atomics.
__global__ void hist_kernel(const void* __restrict__ rows) {
    int base = (blockIdx.x * blockDim.x + threadIdx.x) * 4;
    if (base >= N_EDGES) return;
    int is64 = g_is64;
    int n = min(4, N_EDGES - base);
    int r[4];
#pragma unroll
    for (int j = 0; j < 4; j++)
        if (j < n) r[j] = load_idx(rows, base + j, is64);
#pragma unroll
    for (int j = 0; j < 4; j++)
        if (j < n && (unsigned)r[j] < (unsigned)N_NODES)
            atomicAdd(&g_counts[r[j]], 1);
}

// Single-block exclusive scan; 4 elements/thread via int4 (13 iterations).
#define SCAN_I4 (N_NODES / 4)     // 12500 int4 chunks (N_NODES % 4 == 0)
__global__ __launch_bounds__(1024) void scan_kernel() {
    __shared__ int s_warp[32];
    __shared__ int s_total;
    const int tid = threadIdx.x, lane = tid & 31, wid = tid >> 5;
    int carry = 0;
    for (int base = 0; base < SCAN_I4; base += 1024) {
        int i4 = base + tid;
        int4 v = (i4 < SCAN_I4) ? ((const int4*)g_counts)[i4]
                                : make_int4(0, 0, 0, 0);
        int t = v.x + v.y + v.z + v.w;
        int sum = t;
#pragma unroll
        for (int off = 1; off < 32; off <<= 1) {
            int n = __shfl_up_sync(0xffffffffu, sum, off);
            if (lane >= off) sum += n;
        }
        if (lane == 31) s_warp[wid] = sum;
        __syncthreads();
        if (wid == 0) {
            int w = s_warp[lane];
            int iw = w;
#pragma unroll
            for (int off = 1; off < 32; off <<= 1) {
                int n = __shfl_up_sync(0xffffffffu, iw, off);
                if (lane >= off) iw += n;
            }
            s_warp[lane] = iw - w;  // exclusive warp offsets
            if (lane == 31) s_total = iw;
        }
        __syncthreads();
        if (i4 < SCAN_I4) {
            int e0 = carry + s_warp[wid] + (sum - t);
            int4 ex = make_int4(e0, e0 + v.x, e0 + v.x + v.y, e0 + v.x + v.y + v.z);
            ((int4*)g_row_ptr)[i4] = ex;
            ((int4*)g_cursor)[i4]  = ex;
        }
        carry += s_total;
        __syncthreads();  // protect s_warp/s_total for next chunk
    }
    if (tid == 0) g_row_ptr[N_NODES] = carry;
}

__global__ void scatter_kernel(const void* __restrict__ rows,
                               const void* __restrict__ cols,
                               const float* __restrict__ vals) {
    int i = blockIdx.x * blockDim.x + threadIdx.x;
    if (i < N_EDGES) {
        int is64 = g_is64;
        int r = load_idx(rows, i, is64);
        int c = load_idx(cols, i, is64);
        if ((unsigned)r >= (unsigned)N_NODES) return;
        int p = atomicAdd(&g_cursor[r], 1);
        if ((unsigned)p < (unsigned)N_EDGES)
            g_pairs[p] = make_int2(c, __float_as_int(vals[i]));
    }
}

// ---------------- gather SpMM + gating -------------------------------------
// One warp per output row; lane handles 4 channels (float4).
// 4-deep edge pipeline: 8 gathers + 4 next-pair loads in flight per warp.
__global__ __launch_bounds__(256) void spmm_kernel(float* __restrict__ out) {
    int warp_id = (blockIdx.x * blockDim.x + threadIdx.x) >> 5;
    int lane = threadIdx.x & 31;
    if (warp_id >= N_NODES) return;
    int s = g_row_ptr[warp_id];
    int e = g_row_ptr[warp_id + 1];
    const float* supB = g_support + lane * 4;
    const float* gatB = g_gate + lane * 4;
    float4 aS = make_float4(0.f, 0.f, 0.f, 0.f);
    float4 aG = make_float4(0.f, 0.f, 0.f, 0.f);

    int i = s;
    int2 p0, p1, p2, p3;
    if (i + 4 <= e) {
        p0 = g_pairs[i]; p1 = g_pairs[i + 1];
        p2 = g_pairs[i + 2]; p3 = g_pairs[i + 3];
    }
    while (i + 4 <= e) {
        int2 q0 = p0, q1 = p1, q2 = p2, q3 = p3;
        int j = i + 4;
        if (j + 4 <= e) {
            p0 = g_pairs[j]; p1 = g_pairs[j + 1];
            p2 = g_pairs[j + 2]; p3 = g_pairs[j + 3];
        }
        float4 s0 = *(const float4*)(supB + (long)q0.x * OUT_CH);
        float4 g0 = *(const float4*)(gatB + (long)q0.x * OUT_CH);
        float4 s1 = *(const float4*)(supB + (long)q1.x * OUT_CH);
        float4 g1 = *(const float4*)(gatB + (long)q1.x * OUT_CH);
        float4 s2 = *(const float4*)(supB + (long)q2.x * OUT_CH);
        float4 g2 = *(const float4*)(gatB + (long)q2.x * OUT_CH);
        float4 s3 = *(const float4*)(supB + (long)q3.x * OUT_CH);
        float4 g3 = *(const float4*)(gatB + (long)q3.x * OUT_CH);
        float v0 = __int_as_float(q0.y), v1 = __int_as_float(q1.y);
        float v2 = __int_as_float(q2.y), v3 = __int_as_float(q3.y);
        aS.x += v0 * s0.x; aS.y += v0 * s0.y; aS.z += v0 * s0.z; aS.w += v0 * s0.w;
        aG.x += v0 * g0.x; aG.y += v0 * g0.y; aG.z += v0 * g0.z; aG.w += v0 * g0.w;
        aS.x += v1 * s1.x; aS.y += v1 * s1.y; aS.z += v1 * s1.z; aS.w += v1 * s1.w;
        aG.x += v1 * g1.x; aG.y += v1 * g1.y; aG.z += v1 * g1.z; aG.w += v1 * g1.w;
        aS.x += v2 * s2.x; aS.y += v2 * s2.y; aS.z += v2 * s2.z; aS.w += v2 * s2.w;
        aG.x += v2 * g2.x; aG.y += v2 * g2.y; aG.z += v2 * g2.z; aG.w += v2 * g2.w;
        aS.x += v3 * s3.x; aS.y += v3 * s3.y; aS.z += v3 * s3.z; aS.w += v3 * s3.w;
        aG.x += v3 * g3.x; aG.y += v3 * g3.y; aG.z += v3 * g3.z; aG.w += v3 * g3.w;
        i = j;
    }
    for (; i < e; i++) {
        int2 q = g_pairs[i];
        float v = __int_as_float(q.y);
        float4 sv = *(const float4*)(supB + (long)q.x * OUT_CH);
        float4 gv = *(const float4*)(gatB + (long)q.x * OUT_CH);
        aS.x += v * sv.x; aS.y += v * sv.y; aS.z += v * sv.z; aS.w += v * sv.w;
        aG.x += v * gv.x; aG.y += v * gv.y; aG.z += v * gv.z; aG.w += v * gv.w;
    }
    float4 o;
    o.x = aS.x / (1.0f + __expf(-aG.x));
    o.y = aS.y / (1.0f + __expf(-aG.y));
    o.z = aS.z / (1.0f + __expf(-aG.z));
    o.w = aS.w / (1.0f + __expf(-aG.w));
    *(float4*)&out[(long)warp_id * OUT_CH + lane * 4] = o;
}

// ---------------- launch ----------------------------------------------------
// Two independent chains forked onto parallel graph branches:
//   A (capture stream): zero_detect -> hist -> scan -> scatter
//   B (side stream):    prep_w -> gemm
// spmm joins both.
extern "C" void kernel_launch(void* const* d_in, const int* in_sizes, int n_in,
                              void* d_out, int out_size) {
    const float* x   = (const float*)d_in[0];
    const void*  er  = d_in[1];
    const void*  ec  = d_in[2];
    const float* ev  = (const float*)d_in[3];
    const float* w   = (const float*)d_in[4];
    const float* gw  = (const float*)d_in[5];
    float* out = (float*)d_out;

    cudaFuncSetAttribute(gemm_mma_kernel,
                         cudaFuncAttributeMaxDynamicSharedMemorySize, GEMM_SMEM);

    cudaStream_t sB;
    cudaStreamCreateWithFlags(&sB, cudaStreamNonBlocking);
    cudaEvent_t eFork, eJoin;
    cudaEventCreateWithFlags(&eFork, cudaEventDisableTiming);
    cudaEventCreateWithFlags(&eJoin, cudaEventDisableTiming);

    // Fork: side stream B runs the GEMM chain.
    cudaEventRecord(eFork, 0);
    cudaStreamWaitEvent(sB, eFork, 0);
    prep_w_kernel<<<(IN_CH * OUT_CH + 255) / 256, 256, 0, sB>>>(w, gw);
    gemm_mma_kernel<<<(N_NODES + 127) / 128, 256, GEMM_SMEM, sB>>>(x);
    cudaEventRecord(eJoin, sB);

    // Chain A on the capture (legacy) stream: CSR build.
    zero_detect_kernel<<<(N_NODES + 255) / 256, 256>>>((const unsigned int*)er);
    hist_kernel<<<(N_EDGES / 4 + 255) / 256, 256>>>(er);
    scan_kernel<<<1, 1024>>>();
    scatter_kernel<<<(N_EDGES + 255) / 256, 256>>>(er, ec, ev);

    // Join and run the dependent SpMM.
    cudaStreamWaitEvent(0, eJoin, 0);
    spmm_kernel<<<(N_NODES * 32 + 255) / 256, 256>>>(out);
}